// round 14
// baseline (speedup 1.0000x reference)
#include <cuda_runtime.h>
#include <cuda_bf16.h>

// SimSiam loss, algebraically reduced:
//   loss = -0.5 * sum_c( P_c . Z_c  -  sum_{i in c} pn_i.zn_i ) / npairs
// where P_c/Z_c are per-class sums of L2-normalized rows and
// npairs = sum_c m_c*(m_c-1)/2.   O(n*d) work, no 8192x8192 GEMM.
//
// Champion (12.32us) body + PDL, with ONE change under test: final's
// 512 lane-0 atomics to the single addresses g_S/g_pairs (a serialized
// L2 funnel, ~32cyc each ~= final's entire 7.5us) are redirected to
// per-block slots (8-way contention, 64 slots). Atomics still issue
// early per warp (no pre-reduce sync). Last-done block gathers the 64
// slots in parallel. Everything else is byte-identical to the champion.
//
// Scratch invariant: all accumulated __device__ scratch is ZERO at
// kernel_launch entry (zero at module load; final_kernel re-zeros).

#define NCLASS 512
#define D      128
#define EPS    1e-8f
#define FBLK   64

__device__ float              g_P[NCLASS * D];
__device__ float              g_Z[NCLASS * D];
__device__ int                g_cnt[NCLASS];
__device__ double             g_Ddiag;          // sum_i pn_i . zn_i
__device__ double             g_Spart[FBLK];    // per-block dot partials
__device__ unsigned long long g_Ppart[FBLK];    // per-block pair partials
__device__ unsigned int       g_done;

// 128-bit reduction into global memory (sm_90+), no return value.
__device__ __forceinline__ void red_add_v4(float* p, float x, float y, float z, float w) {
    asm volatile("red.global.add.v4.f32 [%0], {%1, %2, %3, %4};"
                 :: "l"(p), "f"(x), "f"(y), "f"(z), "f"(w) : "memory");
}

// ---------------------------------------------------------------------------
// One warp per row: float4 loads, warp-reduce norms + dot, scatter normalized
// rows into per-class sums with 128-bit vector atomics. In-block dtype sniff:
// warp 0 reads the first 64 int64-view slots (512 B, in-bounds either way);
// an int32 buffer misdetects only if 64 consecutive odd labels are 0.
__global__ void accum_kernel(const float* __restrict__ ps,
                             const float* __restrict__ zs,
                             const void*  __restrict__ tgv,
                             int n_rows) {
    __shared__ double sdp[8];
    __shared__ int    s_is64;

    int warp_in_blk = threadIdx.x >> 5;
    int lane        = threadIdx.x & 31;
    int warp        = (blockIdx.x * blockDim.x + threadIdx.x) >> 5;

    if (warp_in_blk == 0) {
        const long long* t64 = (const long long*)tgv;
        int nslots = n_rows / 2;
        int k = (nslots < 64) ? nslots : 64;
        int bad = 0;
        for (int i = lane; i < k; i += 32) {
            long long v = __ldg(&t64[i]);
            if (v < 0 || v >= NCLASS) bad = 1;
        }
        bad = __any_sync(0xFFFFFFFFu, bad);
        if (lane == 0) s_is64 = !bad;
    }
    __syncthreads();
    int is64 = s_is64;

    double diag = 0.0;
    if (warp < n_rows) {
        float4 a = reinterpret_cast<const float4*>(ps)[warp * (D / 4) + lane];
        float4 b = reinterpret_cast<const float4*>(zs)[warp * (D / 4) + lane];

        float sa = a.x * a.x + a.y * a.y + a.z * a.z + a.w * a.w;
        float sb = b.x * b.x + b.y * b.y + b.z * b.z + b.w * b.w;
        float dp = a.x * b.x + a.y * b.y + a.z * b.z + a.w * b.w;

        #pragma unroll
        for (int o = 16; o > 0; o >>= 1) {
            sa += __shfl_xor_sync(0xFFFFFFFFu, sa, o);
            sb += __shfl_xor_sync(0xFFFFFFFFu, sb, o);
            dp += __shfl_xor_sync(0xFFFFFFFFu, dp, o);
        }

        float invp = 1.0f / fmaxf(sqrtf(sa), EPS);
        float invz = 1.0f / fmaxf(sqrtf(sb), EPS);

        int t;
        if (is64) t = (int)reinterpret_cast<const long long*>(tgv)[warp];
        else      t = reinterpret_cast<const int*>(tgv)[warp];

        red_add_v4(&g_P[t * D + lane * 4], a.x * invp, a.y * invp, a.z * invp, a.w * invp);
        red_add_v4(&g_Z[t * D + lane * 4], b.x * invz, b.y * invz, b.z * invz, b.w * invz);

        if (lane == 0) {
            atomicAdd(&g_cnt[t], 1);
            diag = (double)(dp * invp * invz);
        }
    }
    if (lane == 0) sdp[warp_in_blk] = diag;
    __syncthreads();
    if (threadIdx.x == 0) {
        double s = sdp[0] + sdp[1] + sdp[2] + sdp[3]
                 + sdp[4] + sdp[5] + sdp[6] + sdp[7];
        atomicAdd(&g_Ddiag, s);
    }
}

// ---------------------------------------------------------------------------
// PDL consumer. Per-class dot (warp per class) + pair count into PER-BLOCK
// slots (kills the single-address funnel) + scratch re-zero + last-block
// parallel epilogue. grid = FBLK blocks of 256 threads.
__global__ void final_kernel(float* __restrict__ out, int n_blocks) {
    int lane = threadIdx.x & 31;
    int wid  = threadIdx.x >> 5;                 // 0..7
    int c    = blockIdx.x * 8 + wid;             // class handled by this warp
    int idx  = c * (D / 4) + lane;               // float4 index into g_P/g_Z

    // Wait for accum_kernel's writes to be visible (PDL dependency).
    cudaGridDependencySynchronize();

    float4 p = reinterpret_cast<const float4*>(g_P)[idx];
    float4 z = reinterpret_cast<const float4*>(g_Z)[idx];
    float dot = p.x * z.x + p.y * z.y + p.z * z.z + p.w * z.w;
    #pragma unroll
    for (int o = 16; o > 0; o >>= 1)
        dot += __shfl_xor_sync(0xFFFFFFFFu, dot, o);

    if (lane == 0) {
        atomicAdd(&g_Spart[blockIdx.x], (double)dot);   // 8-way, 64 slots
        unsigned long long m = (unsigned long long)g_cnt[c];
        if (m > 1ull) atomicAdd(&g_Ppart[blockIdx.x], m * (m - 1ull) / 2ull);
    }

    // Re-zero the slices this block owns (restores launch-entry invariant).
    float4 zero4 = make_float4(0.f, 0.f, 0.f, 0.f);
    reinterpret_cast<float4*>(g_P)[idx] = zero4;
    reinterpret_cast<float4*>(g_Z)[idx] = zero4;
    if (lane == 0) g_cnt[c] = 0;

    __syncthreads();
    __threadfence();
    __shared__ int s_last;
    if (threadIdx.x == 0) {
        unsigned int done = atomicAdd(&g_done, 1u);
        s_last = (done == (unsigned int)(n_blocks - 1));
    }
    __syncthreads();

    if (s_last) {
        __threadfence();                       // observe all blocks' atomics
        double             sv = 0.0;
        unsigned long long pv = 0ull;
        if (threadIdx.x < FBLK) {
            sv = g_Spart[threadIdx.x];
            pv = g_Ppart[threadIdx.x];
            g_Spart[threadIdx.x] = 0.0;        // re-zero scratch
            g_Ppart[threadIdx.x] = 0ull;
        }
        #pragma unroll
        for (int o = 16; o > 0; o >>= 1) {
            sv += __shfl_xor_sync(0xFFFFFFFFu, sv, o);
            pv += __shfl_xor_sync(0xFFFFFFFFu, pv, o);
        }
        __shared__ double sv1; __shared__ unsigned long long pv1;
        if (threadIdx.x == 32) { sv1 = sv; pv1 = pv; }
        __syncthreads();
        if (threadIdx.x == 0) {
            double S  = sv + sv1 - g_Ddiag;
            unsigned long long pr = pv + pv1;
            double np = (pr > 0ull) ? (double)pr : 1.0;
            out[0] = (float)(-0.5 * S / np);
            g_Ddiag = 0.0; g_done = 0u;
        }
    }
}

// ---------------------------------------------------------------------------
extern "C" void kernel_launch(void* const* d_in, const int* in_sizes, int n_in,
                              void* d_out, int out_size) {
    const float* ps  = (const float*)d_in[0];
    const float* zs  = (const float*)d_in[1];
    const void*  tgt = d_in[2];
    float*       out = (float*)d_out;

    int n_rows = in_sizes[0] / D;   // 8192

    accum_kernel<<<(n_rows + 7) / 8, 256>>>(ps, zs, tgt, n_rows);

    // PDL: final_kernel scheduled during accum; blocks at grid sync.
    cudaLaunchConfig_t cfg = {};
    cfg.gridDim  = dim3(FBLK, 1, 1);
    cfg.blockDim = dim3(256, 1, 1);
    cfg.dynamicSmemBytes = 0;
    cfg.stream = 0;
    cudaLaunchAttribute attrs[1];
    attrs[0].id = cudaLaunchAttributeProgrammaticStreamSerialization;
    attrs[0].val.programmaticStreamSerializationAllowed = 1;
    cfg.attrs = attrs;
    cfg.numAttrs = 1;
    cudaLaunchKernelEx(&cfg, final_kernel, out, FBLK);
}